// round 15
// baseline (speedup 1.0000x reference)
#include <cuda_runtime.h>
#include <cuda.h>
#include <cuda_fp16.h>
#include <cstdint>
#include <cstddef>

// ---------------------------------------------------------------------------
// Problem constants
// ---------------------------------------------------------------------------
#define B_DIM 4096
#define F_DIM 4096
#define O_DIM 32000
#define NBLK  (O_DIM / 64)     // 500 column blocks of 64

// Scratch (device globals: allocation-free rule)
__device__ __half g_a16[(size_t)B_DIM * F_DIM];    // fp16 a = x - mask
__device__ __half g_b16[(size_t)O_DIM * F_DIM];    // fp16 b = quant(w) - mask (EXACT)
__device__ __half g_l16[(size_t)B_DIM * O_DIM];    // fp16 logits (GEMM out)
__device__ __half g_blkmax[(size_t)B_DIM * NBLK];  // per-(row, 64col-block) max

// ---------------------------------------------------------------------------
// PTX helpers (baseline-PTX only: compute_103 toolchain, no tcgen05.
// R15: 2 CTAs/SM (STAGES=2, regs<=112) so one CTA's stalls are filled by the
// other's HMMAs -- targets the persistent ~10% tensor-pipe idle.)
// ---------------------------------------------------------------------------
__device__ __forceinline__ uint32_t smem_u32(const void* p) {
    uint32_t a;
    asm("{ .reg .u64 t; cvta.to.shared.u64 t, %1; cvt.u32.u64 %0, t; }"
        : "=r"(a) : "l"(p));
    return a;
}

__device__ __forceinline__ uint32_t elect1() {
    uint32_t r;
    asm volatile(
        "{\n\t.reg .pred p;\n\telect.sync _|p, 0xFFFFFFFF;\n\tselp.b32 %0, 1, 0, p;\n\t}"
        : "=r"(r));
    return r;
}

#define MBARRIER_INIT(addr, cnt) \
    asm volatile("mbarrier.init.shared.b64 [%0], %1;" :: "r"((uint32_t)(addr)), "r"((uint32_t)(cnt)) : "memory")

#define MBARRIER_ARRIVE(addr) \
    asm volatile("mbarrier.arrive.shared.b64 _, [%0];" :: "r"((uint32_t)(addr)) : "memory")

#define MBARRIER_EXPECT_TX(addr, bytes) \
    asm volatile("mbarrier.arrive.expect_tx.shared.b64 _, [%0], %1;" :: "r"((uint32_t)(addr)), "r"((uint32_t)(bytes)) : "memory")

#define MBARRIER_WAIT_PARITY(mbar, par) do { \
    uint32_t _m = (uint32_t)(mbar); uint32_t _p = (uint32_t)(par); uint32_t _d; \
    asm volatile("{\n\t.reg .pred p;\n\t" \
        "mbarrier.try_wait.parity.acquire.cta.shared::cta.b64 p, [%1], %2;\n\t" \
        "selp.b32 %0, 1, 0, p;\n\t}" : "=r"(_d) : "r"(_m), "r"(_p) : "memory"); \
    if (!_d) { \
        asm volatile("{\n\t.reg .pred P1;\n\t" \
            "WL_%=:\n\t" \
            "mbarrier.try_wait.parity.acquire.cta.shared::cta.b64 P1, [%0], %1, 0x989680;\n\t" \
            "@P1 bra.uni WD_%=;\n\t" \
            "bra.uni WL_%=;\n\t" \
            "WD_%=:\n\t}" :: "r"(_m), "r"(_p) : "memory"); \
    } \
} while (0)

#define MBARRIER_WAIT_PARITY_RELAXED(mbar, par) do { \
    uint32_t _m = (uint32_t)(mbar); uint32_t _p = (uint32_t)(par); uint32_t _d; \
    asm volatile("{\n\t.reg .pred p;\n\t" \
        "mbarrier.try_wait.parity.relaxed.cta.shared::cta.b64 p, [%1], %2, 0x989680;\n\t" \
        "selp.b32 %0, 1, 0, p;\n\t}" : "=r"(_d) : "r"(_m), "r"(_p) : "memory"); \
    if (!_d) { \
        asm volatile("{\n\t.reg .pred P1;\n\t" \
            "WL_%=:\n\t" \
            "mbarrier.try_wait.parity.relaxed.cta.shared::cta.b64 P1, [%0], %1, 0x989680;\n\t" \
            "@P1 bra.uni WD_%=;\n\t" \
            "bra.uni WL_%=;\n\t" \
            "WD_%=:\n\t}" :: "r"(_m), "r"(_p) : "memory"); \
    } \
} while (0)

__device__ __forceinline__ void tma2d(uint32_t dst, const CUtensorMap* m, int cx, int cy, uint32_t bar) {
    asm volatile(
        "cp.async.bulk.tensor.2d.shared::cta.global.tile.mbarrier::complete_tx::bytes "
        "[%0], [%1, {%2, %3}], [%4];"
        :: "r"(dst), "l"(m), "r"(cx), "r"(cy), "r"(bar) : "memory");
}

#define LDMATRIX_X4(r0, r1, r2, r3, addr) \
    asm volatile("ldmatrix.sync.aligned.m8n8.x4.shared.b16 {%0,%1,%2,%3}, [%4];" \
                 : "=r"(r0), "=r"(r1), "=r"(r2), "=r"(r3) : "r"(addr))

#define MMAF16(c, a, b) \
    asm volatile("mma.sync.aligned.m16n8k16.row.col.f16.f16.f16.f16 " \
                 "{%0,%1}, {%2,%3,%4,%5}, {%6,%7}, {%0,%1};" \
                 : "+r"((c)[0]), "+r"((c)[1]) \
                 : "r"((a)[0]), "r"((a)[1]), "r"((a)[2]), "r"((a)[3]), \
                   "r"((b)[0]), "r"((b)[1]))

// ---------------------------------------------------------------------------
// Fused prep kernel: first B*F/4 threads do a, rest do b.
// ---------------------------------------------------------------------------
__device__ __forceinline__ float quantw1(float w, float m) {
    float q = rintf(w * 128.0f) * 0.0078125f;     // round-half-even like jnp.round
    q = fminf(1.0f, fmaxf(-1.0f, q));
    return q - m;                                  // multiple of 1/128, EXACT in fp16
}

static constexpr size_t A_QUADS = (size_t)B_DIM * F_DIM / 4;   // 4.19M
static constexpr size_t B_QUADS = (size_t)O_DIM * F_DIM / 4;   // 32.77M

__global__ void prep_kernel(const float4* __restrict__ x,
                            const float4* __restrict__ w,
                            const float4* __restrict__ mask) {
    size_t i = (size_t)blockIdx.x * blockDim.x + threadIdx.x;
    if (i < A_QUADS) {
        float4 xv = x[i], mv = mask[i];
        __half2* o = reinterpret_cast<__half2*>(&g_a16[4 * i]);
        o[0] = __floats2half2_rn(xv.x - mv.x, xv.y - mv.y);
        o[1] = __floats2half2_rn(xv.z - mv.z, xv.w - mv.w);
    } else {
        size_t j = i - A_QUADS;
        if (j >= B_QUADS) return;
        float4 wv = w[j], mv = mask[j];
        __half2* o = reinterpret_cast<__half2*>(&g_b16[4 * j]);
        o[0] = __floats2half2_rn(quantw1(wv.x, mv.x), quantw1(wv.y, mv.y));
        o[1] = __floats2half2_rn(quantw1(wv.z, mv.z), quantw1(wv.w, mv.w));
    }
}

// ---------------------------------------------------------------------------
// GEMM: logits16 = a16 @ b16^T (fp16 HMMA, fp16 accum) + per-block maxes +
// zeroing of this tile's region of d_out.
// BM=128, BN=256, BK=64, STAGES=2, 2 CTAs/SM.
// ---------------------------------------------------------------------------
static constexpr int BM = 128, BN = 256, BK = 64, STAGES = 2;
static constexpr int NCHUNK = F_DIM / BK;                          // 64
static constexpr uint32_t A_BYTES = BM * BK * 2;                   // 16384
static constexpr uint32_t B_BYTES = BN * BK * 2;                   // 32768
static constexpr uint32_t STAGE_BYTES = A_BYTES + B_BYTES;         // 49152
static constexpr uint32_t GEMM_SMEM = 1024 + STAGES * STAGE_BYTES; // 99328
static constexpr int GEMM_THREADS = 288;

__global__ void __launch_bounds__(GEMM_THREADS, 2) sgxfl_gemm_kernel(
    const __grid_constant__ CUtensorMap tma_a,
    const __grid_constant__ CUtensorMap tma_b,
    float* __restrict__ out)
{
    extern __shared__ char smem[];
    const uint32_t sb = smem_u32(smem);
    const int tid = threadIdx.x;
    const int wid = tid >> 5, lid = tid & 31;

    const int num_n = O_DIM / BN;   // 125
    const int GROUP = 8;
    const int cpg = GROUP * num_n;  // 1000
    const int g = blockIdx.x / cpg, r = blockIdx.x % cpg;
    const int m0 = (g * GROUP + (r % GROUP)) * BM;
    const int n0 = (r / GROUP) * BN;

    if (tid == 0) {
#pragma unroll
        for (int s = 0; s < STAGES; s++) {
            MBARRIER_INIT(sb + 16 * s, 1);       // full: tx-based
            MBARRIER_INIT(sb + 16 * s + 8, 8);   // empty: 8 math warps
        }
        asm volatile("fence.proxy.async.shared::cta;" ::: "memory");
    }
    __syncthreads();

    if (wid == 8) {
        // ---- TMA producer warp ----
        const uint32_t e1 = elect1();
        int st = 0, ph = 1;
        for (int i = 0; i < NCHUNK; i++) {
            MBARRIER_WAIT_PARITY_RELAXED(sb + 16 * st + 8, ph);
            if (e1) {
                MBARRIER_EXPECT_TX(sb + 16 * st, STAGE_BYTES);
                const uint32_t base = sb + 1024 + st * STAGE_BYTES;
                const int k0 = i * BK;
                tma2d(base,           &tma_a, k0, m0, sb + 16 * st);
                tma2d(base + A_BYTES, &tma_b, k0, n0, sb + 16 * st);
            }
            if (++st == STAGES) { st = 0; ph ^= 1; }
        }
        return;
    }

    // ---- Math warps (0..7): warp tile 64 (M) x 64 (N) -> 2M x 4N grid ----
    const int M0 = (wid & 1) * 64;
    const int N0 = (wid >> 1) * 64;

    const uint32_t xrA  = (uint32_t)(lid & 7) << 4;
    const uint32_t khxA = (uint32_t)(lid >> 4) * 16;
    uint32_t rowA[4];
#pragma unroll
    for (int mi = 0; mi < 4; mi++)
        rowA[mi] = (uint32_t)(M0 + mi * 16 + (lid & 15)) * 128;
    const uint32_t xrB = (uint32_t)(lid & 7) << 4;
    const uint32_t khB = (uint32_t)((lid >> 3) & 1) * 16;
    uint32_t rowB[4];
#pragma unroll
    for (int p = 0; p < 4; p++)
        rowB[p] = (uint32_t)(N0 + p * 16 + (lid & 7) + (lid >> 4) * 8) * 128;

    uint32_t acc[4][8][2];
#pragma unroll
    for (int mi = 0; mi < 4; mi++)
#pragma unroll
        for (int nj = 0; nj < 8; nj++) {
            acc[mi][nj][0] = 0u;
            acc[mi][nj][1] = 0u;
        }

    int st = 0, ph = 0;
#pragma unroll 1
    for (int i = 0; i < NCHUNK; i++) {
        MBARRIER_WAIT_PARITY(sb + 16 * st, ph);
        const uint32_t base = sb + 1024 + st * STAGE_BYTES;
        const uint32_t sA = base, sB = base + A_BYTES;

#pragma unroll
        for (int k = 0; k < 4; k++) {
            const uint32_t colA = (uint32_t)(k * 32) + khxA;
            const uint32_t colB = (uint32_t)(k * 32) + khB;
            uint32_t af[4][4];
#pragma unroll
            for (int mi = 0; mi < 4; mi++) {
                LDMATRIX_X4(af[mi][0], af[mi][1], af[mi][2], af[mi][3],
                            sA + rowA[mi] + (colA ^ xrA));
            }
#pragma unroll
            for (int p = 0; p < 4; p++) {
                uint32_t b0[2], b1[2];
                LDMATRIX_X4(b0[0], b0[1], b1[0], b1[1],
                            sB + rowB[p] + (colB ^ xrB));
#pragma unroll
                for (int mi = 0; mi < 4; mi++) {
                    MMAF16(acc[mi][2 * p],     af[mi], b0);
                    MMAF16(acc[mi][2 * p + 1], af[mi], b1);
                }
            }
        }
        if (lid == 0) MBARRIER_ARRIVE(sb + 16 * st + 8);
        if (++st == STAGES) { st = 0; ph ^= 1; }
    }

    // ---- Zero this tile's region of d_out (spare DRAM BW) ----
    {
        const float4 z4 = make_float4(0.0f, 0.0f, 0.0f, 0.0f);
        float4* o4 = reinterpret_cast<float4*>(out + (size_t)m0 * O_DIM + n0);
        const int stride4 = O_DIM / 4;
#pragma unroll 1
        for (int j = tid; j < BM * (BN / 4); j += 256) {
            const int rr = j >> 6;
            const int cc = j & 63;
            o4[(size_t)rr * stride4 + cc] = z4;
        }
    }

    // ---- Epilogue: store fp16 logits + per-(row, 64col) block maxes ----
    const int rg = lid >> 2;
    const int cg = (lid & 3) * 2;
    const int blk = (n0 + N0) / 64;
#pragma unroll
    for (int mi = 0; mi < 4; mi++) {
        const int row0 = m0 + M0 + mi * 16 + rg;
        __half* q0 = g_l16 + (size_t)row0 * O_DIM + (n0 + N0 + cg);
        __half* q1 = q0 + (size_t)8 * O_DIM;
        __half2 h0 = *reinterpret_cast<__half2*>(&acc[mi][0][0]);
        __half2 h1 = *reinterpret_cast<__half2*>(&acc[mi][0][1]);
#pragma unroll
        for (int nj = 0; nj < 8; nj++) {
            *reinterpret_cast<uint32_t*>(q0 + nj * 8) = acc[mi][nj][0];
            *reinterpret_cast<uint32_t*>(q1 + nj * 8) = acc[mi][nj][1];
            if (nj) {
                h0 = __hmax2(h0, *reinterpret_cast<__half2*>(&acc[mi][nj][0]));
                h1 = __hmax2(h1, *reinterpret_cast<__half2*>(&acc[mi][nj][1]));
            }
        }
        float r0 = fmaxf(__low2float(h0), __high2float(h0));
        float r1 = fmaxf(__low2float(h1), __high2float(h1));
#pragma unroll
        for (int o = 1; o < 4; o <<= 1) {
            r0 = fmaxf(r0, __shfl_xor_sync(~0u, r0, o));
            r1 = fmaxf(r1, __shfl_xor_sync(~0u, r1, o));
        }
        if ((lid & 3) == 0) {   // unique (row, blk) writer -> plain store
            g_blkmax[(size_t)row0 * NBLK + blk]       = __float2half(r0);
            g_blkmax[(size_t)(row0 + 8) * NBLK + blk] = __float2half(r1);
        }
    }
}

// ---------------------------------------------------------------------------
// Sparse candidates-only softmax. Row max from per-block maxes; only blocks
// whose blkmax clears the threshold are read; only candidates are written
// (d_out already zeroed by the GEMM).
// ---------------------------------------------------------------------------
__device__ __forceinline__ float fexp(float x) {
    x = fmaxf(x, -87.0f);
    float t = x * 1.4426950408889634f;
    float fi = floorf(t);
    float f = t - fi;
    float p = 1.5403530e-4f;
    p = fmaf(p, f, 1.3333558e-3f);
    p = fmaf(p, f, 9.6181291e-3f);
    p = fmaf(p, f, 5.5504109e-2f);
    p = fmaf(p, f, 2.4022651e-1f);
    p = fmaf(p, f, 6.9314718e-1f);
    p = fmaf(p, f, 1.0f);
    int ei = (int)fi;
    float sc = __int_as_float((ei + 127) << 23);
    return p * sc;
}

static constexpr int   SMXT = 512;
static constexpr int   FIX_CAP = 1024;
static constexpr float FIX_DELTA = 30.0f;   // 15 sigma of fp16-accum noise
static constexpr uint32_t OFF_AROW = 0;
static constexpr uint32_t OFF_BM   = 16384;
static constexpr uint32_t OFF_RED  = OFF_BM + 1024;
static constexpr uint32_t OFF_LIST = OFF_RED + 256;
static constexpr uint32_t OFF_FIXV = OFF_LIST + 4096;
static constexpr uint32_t OFF_CNT  = OFF_FIXV + 4096;
static constexpr uint32_t SMX_SMEM = OFF_CNT + 16;   // ~26 KB -> 4+ CTAs/SM

__global__ void __launch_bounds__(SMXT, 4) softmax_fix_kernel(
    float* __restrict__ out,
    const float* __restrict__ x,
    const float* __restrict__ mask)
{
    extern __shared__ char sm8[];
    float*  arow = reinterpret_cast<float*>(sm8 + OFF_AROW);
    __half* sbm  = reinterpret_cast<__half*>(sm8 + OFF_BM);
    float*  red  = reinterpret_cast<float*>(sm8 + OFF_RED);
    int*    list = reinterpret_cast<int*>(sm8 + OFF_LIST);
    float*  fixv = reinterpret_cast<float*>(sm8 + OFF_FIXV);
    int*    cnt  = reinterpret_cast<int*>(sm8 + OFF_CNT);

    const int tid = threadIdx.x;
    const int wid = tid >> 5, lid = tid & 31;
    const int row = blockIdx.x;
    float* p = out + (size_t)row * O_DIM;

    if (tid == 0) *cnt = 0;

    // stage a_row = x[row] - mask[row] (fp32, exact; matches reference)
    {
        const float4* xr = reinterpret_cast<const float4*>(x + (size_t)row * F_DIM);
        const float4* mr = reinterpret_cast<const float4*>(mask + (size_t)row * F_DIM);
        for (int j = tid; j < F_DIM / 4; j += SMXT) {
            float4 xv = xr[j], mv = mr[j];
            reinterpret_cast<float4*>(arow)[j] =
                make_float4(xv.x - mv.x, xv.y - mv.y, xv.z - mv.z, xv.w - mv.w);
        }
    }

    // stage block maxes + row max
    const __half* bm = g_blkmax + (size_t)row * NBLK;
    float m = -3.0e38f;
    for (int j = tid; j < NBLK; j += SMXT) {
        __half v = bm[j];
        sbm[j] = v;
        m = fmaxf(m, __half2float(v));
    }
#pragma unroll
    for (int o = 16; o > 0; o >>= 1) m = fmaxf(m, __shfl_xor_sync(~0u, m, o));
    if (lid == 0) red[wid] = m;
    __syncthreads();
    float M0 = red[0];
#pragma unroll
    for (int k = 1; k < SMXT / 32; k++) M0 = fmaxf(M0, red[k]);
    const float thr = M0 - FIX_DELTA;

    // candidate selection: only read logit blocks whose blkmax > thr
    const __half* lrow = g_l16 + (size_t)row * O_DIM;
    for (int blk = tid; blk < NBLK; blk += SMXT) {
        if (__half2float(sbm[blk]) > thr) {
            const uint4* b8 = reinterpret_cast<const uint4*>(lrow + blk * 64);
#pragma unroll 1
            for (int u = 0; u < 8; u++) {            // 8 x uint4 = 64 halves
                uint4 v = b8[u];
                const __half* hv = reinterpret_cast<const __half*>(&v);
#pragma unroll
                for (int q = 0; q < 8; q++) {
                    if (__half2float(hv[q]) > thr) {
                        int pos = atomicAdd(cnt, 1);
                        if (pos < FIX_CAP) list[pos] = blk * 64 + u * 8 + q;
                    }
                }
            }
        }
    }
    __syncthreads();
    int nsel = *cnt;
    if (nsel > FIX_CAP) nsel = FIX_CAP;

    // exact recompute of selected logits: one warp per dot, b from g_b16 (EXACT)
    for (int s = wid; s < nsel; s += SMXT / 32) {
        const int col = list[s];
        const uint4* b4 = reinterpret_cast<const uint4*>(g_b16 + (size_t)col * F_DIM);
        float part = 0.0f;
#pragma unroll 4
        for (int it = 0; it < F_DIM / (8 * 32); it++) {   // 16 iters
            const int c = it * 32 + lid;
            uint4 v = b4[c];
            const float* ar = arow + 8 * c;
            float2 f0 = __half22float2(*reinterpret_cast<__half2*>(&v.x));
            float2 f1 = __half22float2(*reinterpret_cast<__half2*>(&v.y));
            float2 f2 = __half22float2(*reinterpret_cast<__half2*>(&v.z));
            float2 f3 = __half22float2(*reinterpret_cast<__half2*>(&v.w));
            part = fmaf(ar[0], f0.x, part);
            part = fmaf(ar[1], f0.y, part);
            part = fmaf(ar[2], f1.x, part);
            part = fmaf(ar[3], f1.y, part);
            part = fmaf(ar[4], f2.x, part);
            part = fmaf(ar[5], f2.y, part);
            part = fmaf(ar[6], f3.x, part);
            part = fmaf(ar[7], f3.y, part);
        }
#pragma unroll
        for (int o = 16; o > 0; o >>= 1) part += __shfl_xor_sync(~0u, part, o);
        if (lid == 0) fixv[s] = part;
    }
    __syncthreads();

    // exact max over corrected candidates (true max is always among them)
    m = -3.0e38f;
    for (int s = tid; s < nsel; s += SMXT) m = fmaxf(m, fixv[s]);
#pragma unroll
    for (int o = 16; o > 0; o >>= 1) m = fmaxf(m, __shfl_xor_sync(~0u, m, o));
    if (lid == 0) red[wid] = m;
    __syncthreads();
    float M = red[0];
#pragma unroll
    for (int k = 1; k < SMXT / 32; k++) M = fmaxf(M, red[k]);

    // Z from candidates only
    float ssum = 0.0f;
    for (int s = tid; s < nsel; s += SMXT) ssum += fexp(fixv[s] - M);
#pragma unroll
    for (int o = 16; o > 0; o >>= 1) ssum += __shfl_xor_sync(~0u, ssum, o);
    if (lid == 0) red[32 + wid] = ssum;
    __syncthreads();
    float tot = 0.0f;
#pragma unroll
    for (int k = 0; k < SMXT / 32; k++) tot += red[32 + k];
    const float inv = 1.0f / tot;

    // write candidates only (rest of the row zeroed by the GEMM epilogue)
    for (int s = tid; s < nsel; s += SMXT)
        p[list[s]] = fexp(fixv[s] - M) * inv;
}

// ---------------------------------------------------------------------------
// Host launch
// ---------------------------------------------------------------------------
typedef CUresult (*EncodeTiledFn)(
    CUtensorMap*, CUtensorMapDataType, cuuint32_t, void*,
    const cuuint64_t*, const cuuint64_t*, const cuuint32_t*, const cuuint32_t*,
    CUtensorMapInterleave, CUtensorMapSwizzle, CUtensorMapL2promotion, CUtensorMapFloatOOBfill);

static void make_desc2d_f16(EncodeTiledFn enc, CUtensorMap* tm, void* base,
                            uint64_t d0, uint64_t d1, uint32_t b0, uint32_t b1) {
    cuuint64_t dims[2] = {d0, d1};
    cuuint64_t strides[1] = {d0 * 2};  // fp16
    cuuint32_t box[2] = {b0, b1};
    cuuint32_t es[2] = {1, 1};
    enc(tm, CU_TENSOR_MAP_DATA_TYPE_FLOAT16, 2, base, dims, strides, box, es,
        CU_TENSOR_MAP_INTERLEAVE_NONE, CU_TENSOR_MAP_SWIZZLE_128B,
        CU_TENSOR_MAP_L2_PROMOTION_L2_128B, CU_TENSOR_MAP_FLOAT_OOB_FILL_NONE);
}

extern "C" void kernel_launch(void* const* d_in, const int* in_sizes, int n_in,
                              void* d_out, int out_size) {
    const float* x    = (const float*)d_in[0];
    const float* w    = (const float*)d_in[1];
    const float* mask = (const float*)d_in[2];
    float* out = (float*)d_out;

    void *p_a = nullptr, *p_b = nullptr;
    cudaGetSymbolAddress(&p_a, g_a16);
    cudaGetSymbolAddress(&p_b, g_b16);

    EncodeTiledFn enc = nullptr;
    {
        void* fn = nullptr;
        cudaDriverEntryPointQueryResult qr;
        cudaGetDriverEntryPoint("cuTensorMapEncodeTiled", &fn, cudaEnableDefault, &qr);
        enc = (EncodeTiledFn)fn;
    }
    CUtensorMap tma_a, tma_b;
    make_desc2d_f16(enc, &tma_a, p_a, F_DIM, B_DIM, BK, BM);
    make_desc2d_f16(enc, &tma_b, p_b, F_DIM, O_DIM, BK, BN);

    cudaFuncSetAttribute(sgxfl_gemm_kernel, cudaFuncAttributeMaxDynamicSharedMemorySize, GEMM_SMEM);
    cudaFuncSetAttribute(softmax_fix_kernel, cudaFuncAttributeMaxDynamicSharedMemorySize, SMX_SMEM);

    // fused prep: a (B*F/4 quads) then b (O*F/4 quads)
    const size_t total_quads = A_QUADS + B_QUADS;
    prep_kernel<<<(unsigned)((total_quads + 255) / 256), 256>>>(
        (const float4*)x, (const float4*)w, (const float4*)mask);

    const int grid = (B_DIM / BM) * (O_DIM / BN);  // 32*125 = 4000
    sgxfl_gemm_kernel<<<grid, GEMM_THREADS, GEMM_SMEM>>>(tma_a, tma_b, out);

    softmax_fix_kernel<<<B_DIM, SMXT, SMX_SMEM>>>(out, x, mask);
}

// round 16
// speedup vs baseline: 1.0526x; 1.0526x over previous
#include <cuda_runtime.h>
#include <cuda.h>
#include <cuda_fp16.h>
#include <cstdint>
#include <cstddef>

// ---------------------------------------------------------------------------
// Problem constants
// ---------------------------------------------------------------------------
#define B_DIM 4096
#define F_DIM 4096
#define O_DIM 32000
#define NBLK  (O_DIM / 64)     // 500 column blocks of 64

// Scratch (device globals: allocation-free rule)
__device__ __half g_a16[(size_t)B_DIM * F_DIM];    // fp16 a = x - mask
__device__ __half g_b16[(size_t)O_DIM * F_DIM];    // fp16 b = quant(w) - mask (EXACT)
__device__ __half g_l16[(size_t)B_DIM * O_DIM];    // fp16 logits (GEMM out)
__device__ __half g_blkmax[(size_t)B_DIM * NBLK];  // per-(row, 64col-block) max

// ---------------------------------------------------------------------------
// PTX helpers (baseline-PTX only: compute_103 toolchain, no tcgen05.
// R14 config is the measured optimum: STAGES=4, 1 CTA/SM, 89% tensor.
// R16: prep dedups mask reads for rows < B_DIM (one load feeds a16 AND b16).
// ---------------------------------------------------------------------------
__device__ __forceinline__ uint32_t smem_u32(const void* p) {
    uint32_t a;
    asm("{ .reg .u64 t; cvta.to.shared.u64 t, %1; cvt.u32.u64 %0, t; }"
        : "=r"(a) : "l"(p));
    return a;
}

__device__ __forceinline__ uint32_t elect1() {
    uint32_t r;
    asm volatile(
        "{\n\t.reg .pred p;\n\telect.sync _|p, 0xFFFFFFFF;\n\tselp.b32 %0, 1, 0, p;\n\t}"
        : "=r"(r));
    return r;
}

#define MBARRIER_INIT(addr, cnt) \
    asm volatile("mbarrier.init.shared.b64 [%0], %1;" :: "r"((uint32_t)(addr)), "r"((uint32_t)(cnt)) : "memory")

#define MBARRIER_ARRIVE(addr) \
    asm volatile("mbarrier.arrive.shared.b64 _, [%0];" :: "r"((uint32_t)(addr)) : "memory")

#define MBARRIER_EXPECT_TX(addr, bytes) \
    asm volatile("mbarrier.arrive.expect_tx.shared.b64 _, [%0], %1;" :: "r"((uint32_t)(addr)), "r"((uint32_t)(bytes)) : "memory")

#define MBARRIER_WAIT_PARITY(mbar, par) do { \
    uint32_t _m = (uint32_t)(mbar); uint32_t _p = (uint32_t)(par); uint32_t _d; \
    asm volatile("{\n\t.reg .pred p;\n\t" \
        "mbarrier.try_wait.parity.acquire.cta.shared::cta.b64 p, [%1], %2;\n\t" \
        "selp.b32 %0, 1, 0, p;\n\t}" : "=r"(_d) : "r"(_m), "r"(_p) : "memory"); \
    if (!_d) { \
        asm volatile("{\n\t.reg .pred P1;\n\t" \
            "WL_%=:\n\t" \
            "mbarrier.try_wait.parity.acquire.cta.shared::cta.b64 P1, [%0], %1, 0x989680;\n\t" \
            "@P1 bra.uni WD_%=;\n\t" \
            "bra.uni WL_%=;\n\t" \
            "WD_%=:\n\t}" :: "r"(_m), "r"(_p) : "memory"); \
    } \
} while (0)

#define MBARRIER_WAIT_PARITY_RELAXED(mbar, par) do { \
    uint32_t _m = (uint32_t)(mbar); uint32_t _p = (uint32_t)(par); uint32_t _d; \
    asm volatile("{\n\t.reg .pred p;\n\t" \
        "mbarrier.try_wait.parity.relaxed.cta.shared::cta.b64 p, [%1], %2, 0x989680;\n\t" \
        "selp.b32 %0, 1, 0, p;\n\t}" : "=r"(_d) : "r"(_m), "r"(_p) : "memory"); \
    if (!_d) { \
        asm volatile("{\n\t.reg .pred P1;\n\t" \
            "WL_%=:\n\t" \
            "mbarrier.try_wait.parity.relaxed.cta.shared::cta.b64 P1, [%0], %1, 0x989680;\n\t" \
            "@P1 bra.uni WD_%=;\n\t" \
            "bra.uni WL_%=;\n\t" \
            "WD_%=:\n\t}" :: "r"(_m), "r"(_p) : "memory"); \
    } \
} while (0)

__device__ __forceinline__ void tma2d(uint32_t dst, const CUtensorMap* m, int cx, int cy, uint32_t bar) {
    asm volatile(
        "cp.async.bulk.tensor.2d.shared::cta.global.tile.mbarrier::complete_tx::bytes "
        "[%0], [%1, {%2, %3}], [%4];"
        :: "r"(dst), "l"(m), "r"(cx), "r"(cy), "r"(bar) : "memory");
}

#define LDMATRIX_X4(r0, r1, r2, r3, addr) \
    asm volatile("ldmatrix.sync.aligned.m8n8.x4.shared.b16 {%0,%1,%2,%3}, [%4];" \
                 : "=r"(r0), "=r"(r1), "=r"(r2), "=r"(r3) : "r"(addr))

#define MMAF16(c, a, b) \
    asm volatile("mma.sync.aligned.m16n8k16.row.col.f16.f16.f16.f16 " \
                 "{%0,%1}, {%2,%3,%4,%5}, {%6,%7}, {%0,%1};" \
                 : "+r"((c)[0]), "+r"((c)[1]) \
                 : "r"((a)[0]), "r"((a)[1]), "r"((a)[2]), "r"((a)[3]), \
                   "r"((b)[0]), "r"((b)[1]))

// ---------------------------------------------------------------------------
// Fused prep kernel. First A_QUADS threads produce BOTH a16 and b16 for
// rows < B_DIM (mask quad loaded once); remaining threads produce b16 only.
// ---------------------------------------------------------------------------
__device__ __forceinline__ float quantw1(float w, float m) {
    float q = rintf(w * 128.0f) * 0.0078125f;     // round-half-even like jnp.round
    q = fminf(1.0f, fmaxf(-1.0f, q));
    return q - m;                                  // multiple of 1/128, EXACT in fp16
}

static constexpr size_t A_QUADS = (size_t)B_DIM * F_DIM / 4;   // 4.19M
static constexpr size_t B_QUADS = (size_t)O_DIM * F_DIM / 4;   // 32.77M

__global__ void prep_kernel(const float4* __restrict__ x,
                            const float4* __restrict__ w,
                            const float4* __restrict__ mask) {
    size_t i = (size_t)blockIdx.x * blockDim.x + threadIdx.x;
    if (i < A_QUADS) {
        // rows < B_DIM: one mask load feeds both a16 and b16
        float4 xv = x[i], wv = w[i], mv = mask[i];
        __half2* oa = reinterpret_cast<__half2*>(&g_a16[4 * i]);
        oa[0] = __floats2half2_rn(xv.x - mv.x, xv.y - mv.y);
        oa[1] = __floats2half2_rn(xv.z - mv.z, xv.w - mv.w);
        __half2* ob = reinterpret_cast<__half2*>(&g_b16[4 * i]);
        ob[0] = __floats2half2_rn(quantw1(wv.x, mv.x), quantw1(wv.y, mv.y));
        ob[1] = __floats2half2_rn(quantw1(wv.z, mv.z), quantw1(wv.w, mv.w));
    } else {
        size_t j = i;                     // quads A_QUADS..B_QUADS-1: b only
        if (j >= B_QUADS) return;
        float4 wv = w[j], mv = mask[j];
        __half2* o = reinterpret_cast<__half2*>(&g_b16[4 * j]);
        o[0] = __floats2half2_rn(quantw1(wv.x, mv.x), quantw1(wv.y, mv.y));
        o[1] = __floats2half2_rn(quantw1(wv.z, mv.z), quantw1(wv.w, mv.w));
    }
}

// ---------------------------------------------------------------------------
// GEMM: logits16 = a16 @ b16^T (fp16 HMMA, fp16 accum) + per-block maxes +
// zeroing of this tile's region of d_out (spare DRAM BW).
// BM=128, BN=256, BK=64, STAGES=4; 8 math warps (64x64) + 1 TMA warp.
// ---------------------------------------------------------------------------
static constexpr int BM = 128, BN = 256, BK = 64, STAGES = 4;
static constexpr int NCHUNK = F_DIM / BK;                          // 64
static constexpr uint32_t A_BYTES = BM * BK * 2;                   // 16384
static constexpr uint32_t B_BYTES = BN * BK * 2;                   // 32768
static constexpr uint32_t STAGE_BYTES = A_BYTES + B_BYTES;         // 49152
static constexpr uint32_t GEMM_SMEM = 1024 + STAGES * STAGE_BYTES; // 197632
static constexpr int GEMM_THREADS = 288;

__global__ void __launch_bounds__(GEMM_THREADS, 1) sgxfl_gemm_kernel(
    const __grid_constant__ CUtensorMap tma_a,
    const __grid_constant__ CUtensorMap tma_b,
    float* __restrict__ out)
{
    extern __shared__ char smem[];
    const uint32_t sb = smem_u32(smem);
    const int tid = threadIdx.x;
    const int wid = tid >> 5, lid = tid & 31;

    const int num_n = O_DIM / BN;   // 125
    const int GROUP = 8;
    const int cpg = GROUP * num_n;  // 1000
    const int g = blockIdx.x / cpg, r = blockIdx.x % cpg;
    const int m0 = (g * GROUP + (r % GROUP)) * BM;
    const int n0 = (r / GROUP) * BN;

    if (tid == 0) {
#pragma unroll
        for (int s = 0; s < STAGES; s++) {
            MBARRIER_INIT(sb + 16 * s, 1);       // full: tx-based
            MBARRIER_INIT(sb + 16 * s + 8, 8);   // empty: 8 math warps
        }
        asm volatile("fence.proxy.async.shared::cta;" ::: "memory");
    }
    __syncthreads();

    if (wid == 8) {
        // ---- TMA producer warp ----
        const uint32_t e1 = elect1();
        int st = 0, ph = 1;
        for (int i = 0; i < NCHUNK; i++) {
            MBARRIER_WAIT_PARITY_RELAXED(sb + 16 * st + 8, ph);
            if (e1) {
                MBARRIER_EXPECT_TX(sb + 16 * st, STAGE_BYTES);
                const uint32_t base = sb + 1024 + st * STAGE_BYTES;
                const int k0 = i * BK;
                tma2d(base,           &tma_a, k0, m0, sb + 16 * st);
                tma2d(base + A_BYTES, &tma_b, k0, n0, sb + 16 * st);
            }
            if (++st == STAGES) { st = 0; ph ^= 1; }
        }
        return;
    }

    // ---- Math warps (0..7): warp tile 64 (M) x 64 (N) -> 2M x 4N grid ----
    const int M0 = (wid & 1) * 64;
    const int N0 = (wid >> 1) * 64;

    const uint32_t xrA  = (uint32_t)(lid & 7) << 4;
    const uint32_t khxA = (uint32_t)(lid >> 4) * 16;
    uint32_t rowA[4];
#pragma unroll
    for (int mi = 0; mi < 4; mi++)
        rowA[mi] = (uint32_t)(M0 + mi * 16 + (lid & 15)) * 128;
    const uint32_t xrB = (uint32_t)(lid & 7) << 4;
    const uint32_t khB = (uint32_t)((lid >> 3) & 1) * 16;
    uint32_t rowB[4];
#pragma unroll
    for (int p = 0; p < 4; p++)
        rowB[p] = (uint32_t)(N0 + p * 16 + (lid & 7) + (lid >> 4) * 8) * 128;

    uint32_t acc[4][8][2];
#pragma unroll
    for (int mi = 0; mi < 4; mi++)
#pragma unroll
        for (int nj = 0; nj < 8; nj++) {
            acc[mi][nj][0] = 0u;
            acc[mi][nj][1] = 0u;
        }

    int st = 0, ph = 0;
#pragma unroll 1
    for (int i = 0; i < NCHUNK; i++) {
        MBARRIER_WAIT_PARITY(sb + 16 * st, ph);
        const uint32_t base = sb + 1024 + st * STAGE_BYTES;
        const uint32_t sA = base, sB = base + A_BYTES;

#pragma unroll
        for (int k = 0; k < 4; k++) {
            const uint32_t colA = (uint32_t)(k * 32) + khxA;
            const uint32_t colB = (uint32_t)(k * 32) + khB;
            uint32_t af[4][4];
#pragma unroll
            for (int mi = 0; mi < 4; mi++) {
                LDMATRIX_X4(af[mi][0], af[mi][1], af[mi][2], af[mi][3],
                            sA + rowA[mi] + (colA ^ xrA));
            }
#pragma unroll
            for (int p = 0; p < 4; p++) {
                uint32_t b0[2], b1[2];
                LDMATRIX_X4(b0[0], b0[1], b1[0], b1[1],
                            sB + rowB[p] + (colB ^ xrB));
#pragma unroll
                for (int mi = 0; mi < 4; mi++) {
                    MMAF16(acc[mi][2 * p],     af[mi], b0);
                    MMAF16(acc[mi][2 * p + 1], af[mi], b1);
                }
            }
        }
        if (lid == 0) MBARRIER_ARRIVE(sb + 16 * st + 8);
        if (++st == STAGES) { st = 0; ph ^= 1; }
    }

    // ---- Zero this tile's region of d_out (spare DRAM BW) ----
    {
        const float4 z4 = make_float4(0.0f, 0.0f, 0.0f, 0.0f);
        float4* o4 = reinterpret_cast<float4*>(out + (size_t)m0 * O_DIM + n0);
        const int stride4 = O_DIM / 4;
#pragma unroll 1
        for (int j = tid; j < BM * (BN / 4); j += 256) {
            const int rr = j >> 6;
            const int cc = j & 63;
            o4[(size_t)rr * stride4 + cc] = z4;
        }
    }

    // ---- Epilogue: store fp16 logits + per-(row, 64col) block maxes ----
    const int rg = lid >> 2;
    const int cg = (lid & 3) * 2;
    const int blk = (n0 + N0) / 64;
#pragma unroll
    for (int mi = 0; mi < 4; mi++) {
        const int row0 = m0 + M0 + mi * 16 + rg;
        __half* q0 = g_l16 + (size_t)row0 * O_DIM + (n0 + N0 + cg);
        __half* q1 = q0 + (size_t)8 * O_DIM;
        __half2 h0 = *reinterpret_cast<__half2*>(&acc[mi][0][0]);
        __half2 h1 = *reinterpret_cast<__half2*>(&acc[mi][0][1]);
#pragma unroll
        for (int nj = 0; nj < 8; nj++) {
            *reinterpret_cast<uint32_t*>(q0 + nj * 8) = acc[mi][nj][0];
            *reinterpret_cast<uint32_t*>(q1 + nj * 8) = acc[mi][nj][1];
            if (nj) {
                h0 = __hmax2(h0, *reinterpret_cast<__half2*>(&acc[mi][nj][0]));
                h1 = __hmax2(h1, *reinterpret_cast<__half2*>(&acc[mi][nj][1]));
            }
        }
        float r0 = fmaxf(__low2float(h0), __high2float(h0));
        float r1 = fmaxf(__low2float(h1), __high2float(h1));
#pragma unroll
        for (int o = 1; o < 4; o <<= 1) {
            r0 = fmaxf(r0, __shfl_xor_sync(~0u, r0, o));
            r1 = fmaxf(r1, __shfl_xor_sync(~0u, r1, o));
        }
        if ((lid & 3) == 0) {   // unique (row, blk) writer -> plain store
            g_blkmax[(size_t)row0 * NBLK + blk]       = __float2half(r0);
            g_blkmax[(size_t)(row0 + 8) * NBLK + blk] = __float2half(r1);
        }
    }
}

// ---------------------------------------------------------------------------
// Sparse candidates-only softmax. Row max from per-block maxes; only blocks
// whose blkmax clears the threshold are read; only candidates are written
// (d_out already zeroed by the GEMM).
// ---------------------------------------------------------------------------
__device__ __forceinline__ float fexp(float x) {
    x = fmaxf(x, -87.0f);
    float t = x * 1.4426950408889634f;
    float fi = floorf(t);
    float f = t - fi;
    float p = 1.5403530e-4f;
    p = fmaf(p, f, 1.3333558e-3f);
    p = fmaf(p, f, 9.6181291e-3f);
    p = fmaf(p, f, 5.5504109e-2f);
    p = fmaf(p, f, 2.4022651e-1f);
    p = fmaf(p, f, 6.9314718e-1f);
    p = fmaf(p, f, 1.0f);
    int ei = (int)fi;
    float sc = __int_as_float((ei + 127) << 23);
    return p * sc;
}

static constexpr int   SMXT = 512;
static constexpr int   FIX_CAP = 1024;
static constexpr float FIX_DELTA = 30.0f;   // 15 sigma of fp16-accum noise
static constexpr uint32_t OFF_AROW = 0;
static constexpr uint32_t OFF_BM   = 16384;
static constexpr uint32_t OFF_RED  = OFF_BM + 1024;
static constexpr uint32_t OFF_LIST = OFF_RED + 256;
static constexpr uint32_t OFF_FIXV = OFF_LIST + 4096;
static constexpr uint32_t OFF_CNT  = OFF_FIXV + 4096;
static constexpr uint32_t SMX_SMEM = OFF_CNT + 16;   // ~26 KB -> 4+ CTAs/SM

__global__ void __launch_bounds__(SMXT, 4) softmax_fix_kernel(
    float* __restrict__ out,
    const float* __restrict__ x,
    const float* __restrict__ mask)
{
    extern __shared__ char sm8[];
    float*  arow = reinterpret_cast<float*>(sm8 + OFF_AROW);
    __half* sbm  = reinterpret_cast<__half*>(sm8 + OFF_BM);
    float*  red  = reinterpret_cast<float*>(sm8 + OFF_RED);
    int*    list = reinterpret_cast<int*>(sm8 + OFF_LIST);
    float*  fixv = reinterpret_cast<float*>(sm8 + OFF_FIXV);
    int*    cnt  = reinterpret_cast<int*>(sm8 + OFF_CNT);

    const int tid = threadIdx.x;
    const int wid = tid >> 5, lid = tid & 31;
    const int row = blockIdx.x;
    float* p = out + (size_t)row * O_DIM;

    if (tid == 0) *cnt = 0;

    // stage a_row = x[row] - mask[row] (fp32, exact; matches reference)
    {
        const float4* xr = reinterpret_cast<const float4*>(x + (size_t)row * F_DIM);
        const float4* mr = reinterpret_cast<const float4*>(mask + (size_t)row * F_DIM);
        for (int j = tid; j < F_DIM / 4; j += SMXT) {
            float4 xv = xr[j], mv = mr[j];
            reinterpret_cast<float4*>(arow)[j] =
                make_float4(xv.x - mv.x, xv.y - mv.y, xv.z - mv.z, xv.w - mv.w);
        }
    }

    // stage block maxes + row max
    const __half* bm = g_blkmax + (size_t)row * NBLK;
    float m = -3.0e38f;
    for (int j = tid; j < NBLK; j += SMXT) {
        __half v = bm[j];
        sbm[j] = v;
        m = fmaxf(m, __half2float(v));
    }
#pragma unroll
    for (int o = 16; o > 0; o >>= 1) m = fmaxf(m, __shfl_xor_sync(~0u, m, o));
    if (lid == 0) red[wid] = m;
    __syncthreads();
    float M0 = red[0];
#pragma unroll
    for (int k = 1; k < SMXT / 32; k++) M0 = fmaxf(M0, red[k]);
    const float thr = M0 - FIX_DELTA;

    // candidate selection: only read logit blocks whose blkmax > thr
    const __half* lrow = g_l16 + (size_t)row * O_DIM;
    for (int blk = tid; blk < NBLK; blk += SMXT) {
        if (__half2float(sbm[blk]) > thr) {
            const uint4* b8 = reinterpret_cast<const uint4*>(lrow + blk * 64);
#pragma unroll 1
            for (int u = 0; u < 8; u++) {            // 8 x uint4 = 64 halves
                uint4 v = b8[u];
                const __half* hv = reinterpret_cast<const __half*>(&v);
#pragma unroll
                for (int q = 0; q < 8; q++) {
                    if (__half2float(hv[q]) > thr) {
                        int pos = atomicAdd(cnt, 1);
                        if (pos < FIX_CAP) list[pos] = blk * 64 + u * 8 + q;
                    }
                }
            }
        }
    }
    __syncthreads();
    int nsel = *cnt;
    if (nsel > FIX_CAP) nsel = FIX_CAP;

    // exact recompute of selected logits: one warp per dot, b from g_b16 (EXACT)
    for (int s = wid; s < nsel; s += SMXT / 32) {
        const int col = list[s];
        const uint4* b4 = reinterpret_cast<const uint4*>(g_b16 + (size_t)col * F_DIM);
        float part = 0.0f;
#pragma unroll 4
        for (int it = 0; it < F_DIM / (8 * 32); it++) {   // 16 iters
            const int c = it * 32 + lid;
            uint4 v = b4[c];
            const float* ar = arow + 8 * c;
            float2 f0 = __half22float2(*reinterpret_cast<__half2*>(&v.x));
            float2 f1 = __half22float2(*reinterpret_cast<__half2*>(&v.y));
            float2 f2 = __half22float2(*reinterpret_cast<__half2*>(&v.z));
            float2 f3 = __half22float2(*reinterpret_cast<__half2*>(&v.w));
            part = fmaf(ar[0], f0.x, part);
            part = fmaf(ar[1], f0.y, part);
            part = fmaf(ar[2], f1.x, part);
            part = fmaf(ar[3], f1.y, part);
            part = fmaf(ar[4], f2.x, part);
            part = fmaf(ar[5], f2.y, part);
            part = fmaf(ar[6], f3.x, part);
            part = fmaf(ar[7], f3.y, part);
        }
#pragma unroll
        for (int o = 16; o > 0; o >>= 1) part += __shfl_xor_sync(~0u, part, o);
        if (lid == 0) fixv[s] = part;
    }
    __syncthreads();

    // exact max over corrected candidates (true max is always among them)
    m = -3.0e38f;
    for (int s = tid; s < nsel; s += SMXT) m = fmaxf(m, fixv[s]);
#pragma unroll
    for (int o = 16; o > 0; o >>= 1) m = fmaxf(m, __shfl_xor_sync(~0u, m, o));
    if (lid == 0) red[wid] = m;
    __syncthreads();
    float M = red[0];
#pragma unroll
    for (int k = 1; k < SMXT / 32; k++) M = fmaxf(M, red[k]);

    // Z from candidates only
    float ssum = 0.0f;
    for (int s = tid; s < nsel; s += SMXT) ssum += fexp(fixv[s] - M);
#pragma unroll
    for (int o = 16; o > 0; o >>= 1) ssum += __shfl_xor_sync(~0u, ssum, o);
    if (lid == 0) red[32 + wid] = ssum;
    __syncthreads();
    float tot = 0.0f;
#pragma unroll
    for (int k = 0; k < SMXT / 32; k++) tot += red[32 + k];
    const float inv = 1.0f / tot;

    // write candidates only (rest of the row zeroed by the GEMM epilogue)
    for (int s = tid; s < nsel; s += SMXT)
        p[list[s]] = fexp(fixv[s] - M) * inv;
}

// ---------------------------------------------------------------------------
// Host launch
// ---------------------------------------------------------------------------
typedef CUresult (*EncodeTiledFn)(
    CUtensorMap*, CUtensorMapDataType, cuuint32_t, void*,
    const cuuint64_t*, const cuuint64_t*, const cuuint32_t*, const cuuint32_t*,
    CUtensorMapInterleave, CUtensorMapSwizzle, CUtensorMapL2promotion, CUtensorMapFloatOOBfill);

static void make_desc2d_f16(EncodeTiledFn enc, CUtensorMap* tm, void* base,
                            uint64_t d0, uint64_t d1, uint32_t b0, uint32_t b1) {
    cuuint64_t dims[2] = {d0, d1};
    cuuint64_t strides[1] = {d0 * 2};  // fp16
    cuuint32_t box[2] = {b0, b1};
    cuuint32_t es[2] = {1, 1};
    enc(tm, CU_TENSOR_MAP_DATA_TYPE_FLOAT16, 2, base, dims, strides, box, es,
        CU_TENSOR_MAP_INTERLEAVE_NONE, CU_TENSOR_MAP_SWIZZLE_128B,
        CU_TENSOR_MAP_L2_PROMOTION_L2_128B, CU_TENSOR_MAP_FLOAT_OOB_FILL_NONE);
}

extern "C" void kernel_launch(void* const* d_in, const int* in_sizes, int n_in,
                              void* d_out, int out_size) {
    const float* x    = (const float*)d_in[0];
    const float* w    = (const float*)d_in[1];
    const float* mask = (const float*)d_in[2];
    float* out = (float*)d_out;

    void *p_a = nullptr, *p_b = nullptr;
    cudaGetSymbolAddress(&p_a, g_a16);
    cudaGetSymbolAddress(&p_b, g_b16);

    EncodeTiledFn enc = nullptr;
    {
        void* fn = nullptr;
        cudaDriverEntryPointQueryResult qr;
        cudaGetDriverEntryPoint("cuTensorMapEncodeTiled", &fn, cudaEnableDefault, &qr);
        enc = (EncodeTiledFn)fn;
    }
    CUtensorMap tma_a, tma_b;
    make_desc2d_f16(enc, &tma_a, p_a, F_DIM, B_DIM, BK, BM);
    make_desc2d_f16(enc, &tma_b, p_b, F_DIM, O_DIM, BK, BN);

    cudaFuncSetAttribute(sgxfl_gemm_kernel, cudaFuncAttributeMaxDynamicSharedMemorySize, GEMM_SMEM);
    cudaFuncSetAttribute(softmax_fix_kernel, cudaFuncAttributeMaxDynamicSharedMemorySize, SMX_SMEM);

    // fused prep: quads < A_QUADS emit a16 AND b16; rest emit b16 only
    prep_kernel<<<(unsigned)((B_QUADS + 255) / 256), 256>>>(
        (const float4*)x, (const float4*)w, (const float4*)mask);

    const int grid = (B_DIM / BM) * (O_DIM / BN);  // 32*125 = 4000
    sgxfl_gemm_kernel<<<grid, GEMM_THREADS, GEMM_SMEM>>>(tma_a, tma_b, out);

    softmax_fix_kernel<<<B_DIM, SMXT, SMX_SMEM>>>(out, x, mask);
}